// round 2
// baseline (speedup 1.0000x reference)
#include <cuda_runtime.h>

#define TPB 256

// ---- shared-memory layout (floats) ----
// Ww1[2x30]  bw1[30]  Ww2[30x30] bw2[30] Ww3[30x30] bw3[30] Ww4[30x8] bw4[8]
// Wp1[2x15]  bp1[15]  Wp2[15x15] bp2[15] Wp3[15x15] bp3[15] Wp4[15x4] bp4[4]
// imv[2] lmbd[1]
namespace off {
constexpr int W1 = 0,    B1 = 60,   W2 = 90,   B2 = 990,
              W3 = 1020, B3 = 1920, W4 = 1950, B4 = 2190,
              P1 = 2198, PB1 = 2228, P2 = 2243, PB2 = 2468,
              P3 = 2483, PB3 = 2708, P4 = 2723, PB4 = 2783,
              IMV = 2787, LMB = 2789, TOTAL = 2790;
}

// Accurate-enough tanh: 1 EX2 + 1 RCP-path divide + adds (~1e-7 abs error).
__device__ __forceinline__ float fast_tanhf(float v) {
    float a = fabsf(v);
    float e = __expf(-2.0f * a);                 // EX2-based, always in (0,1]
    float r = __fdividef(1.0f - e, 1.0f + e);
    return copysignf(r, v);
}

// Given unit-circle point (c, s) = (cos th, sin th) with s carrying the sign
// of y, produce sin(th/2), cos(th/2) with no cancellation in either regime.
__device__ __forceinline__ void half_angle(float c, float s, float& sh, float& ch) {
    if (c >= 0.0f) {                              // th in [-pi/2, pi/2]
        ch = sqrtf(0.5f * (1.0f + c));            // well conditioned
        sh = __fdividef(s, 2.0f * ch);            // sin th = 2 sh ch
    } else {                                      // th near +-pi
        sh = copysignf(sqrtf(0.5f * (1.0f - c)), s);
        ch = __fdividef(s, 2.0f * sh);            // >= 0 (s, sh share sign)
    }
}

__global__ void __launch_bounds__(TPB)
mlp_interior_kernel(
    const float* __restrict__ x,
    const float* __restrict__ imv,
    const float* __restrict__ lmbd,
    const float* __restrict__ Ww1, const float* __restrict__ bw1,
    const float* __restrict__ Ww2, const float* __restrict__ bw2,
    const float* __restrict__ Ww3, const float* __restrict__ bw3,
    const float* __restrict__ Ww4, const float* __restrict__ bw4,
    const float* __restrict__ Wp1, const float* __restrict__ bp1,
    const float* __restrict__ Wp2, const float* __restrict__ bp2,
    const float* __restrict__ Wp3, const float* __restrict__ bp3,
    const float* __restrict__ Wp4, const float* __restrict__ bp4,
    float* __restrict__ out, int N)
{
    __shared__ float S[off::TOTAL];
    {
        const float* srcs[16] = {Ww1, bw1, Ww2, bw2, Ww3, bw3, Ww4, bw4,
                                 Wp1, bp1, Wp2, bp2, Wp3, bp3, Wp4, bp4};
        const int lens[16] = {60, 30, 900, 30, 900, 30, 240, 8,
                              30, 15, 225, 15, 225, 15, 60, 4};
        int o = 0;
        for (int sg = 0; sg < 16; ++sg) {
            const float* p = srcs[sg];
            const int L = lens[sg];
            for (int k = threadIdx.x; k < L; k += TPB) S[o + k] = p[k];
            o += L;
        }
        if (threadIdx.x == 0) {
            S[off::IMV]     = imv[0];
            S[off::IMV + 1] = imv[1];
            S[off::LMB]     = lmbd[0];
        }
    }
    __syncthreads();

    const int i = blockIdx.x * TPB + threadIdx.x;
    if (i >= N) return;

    const float2 xv = reinterpret_cast<const float2*>(x)[i];
    const float x0 = xv.x, x1 = xv.y;

    // ---------- w MLP: 2 -> 30 -> 30 -> 30 -> 8 ----------
    float h[30], g[30];
    #pragma unroll
    for (int j = 0; j < 30; ++j)
        h[j] = fast_tanhf(fmaf(x0, S[off::W1 + j],
                        fmaf(x1, S[off::W1 + 30 + j], S[off::B1 + j])));
    for (int j = 0; j < 30; ++j) {
        float a = S[off::B2 + j];
        #pragma unroll
        for (int k = 0; k < 30; ++k) a = fmaf(h[k], S[off::W2 + k * 30 + j], a);
        g[j] = fast_tanhf(a);
    }
    for (int j = 0; j < 30; ++j) {
        float a = S[off::B3 + j];
        #pragma unroll
        for (int k = 0; k < 30; ++k) a = fmaf(g[k], S[off::W3 + k * 30 + j], a);
        h[j] = fast_tanhf(a);
    }
    float w[8];
    #pragma unroll
    for (int j = 0; j < 8; ++j) {
        float a = S[off::B4 + j];
        #pragma unroll
        for (int k = 0; k < 30; ++k) a = fmaf(h[k], S[off::W4 + k * 8 + j], a);
        w[j] = a;
    }

    // ---------- geometry ----------
    const float d0 = x0 - S[off::IMV], d1 = x1 - S[off::IMV + 1];
    const float r2 = fmaf(d0, d0, d1 * d1);
    const float r  = sqrtf(r2);
    const float ir = __fdividef(1.0f, r);
    const float bx = d0 * ir, by = d1 * ir;

    // yita(r): smoothstep-style cutoff
    const float t  = fminf(fmaxf(fmaf(2.5f, r, -1.25f), 0.0f), 1.0f);
    const float t3 = t * t * t;
    const float yita = fmaf(fmaf(fmaf(-6.0f, t, 15.0f), t, -10.0f), t3, 1.0f);

    // ---------- phi MLP on unit vector: 2 -> 15 -> 15 -> 15 -> 4 ----------
    float p[15], q[15];
    #pragma unroll
    for (int j = 0; j < 15; ++j)
        p[j] = fast_tanhf(fmaf(bx, S[off::P1 + j],
                        fmaf(by, S[off::P1 + 15 + j], S[off::PB1 + j])));
    for (int j = 0; j < 15; ++j) {
        float a = S[off::PB2 + j];
        #pragma unroll
        for (int k = 0; k < 15; ++k) a = fmaf(p[k], S[off::P2 + k * 15 + j], a);
        q[j] = fast_tanhf(a);
    }
    for (int j = 0; j < 15; ++j) {
        float a = S[off::PB3 + j];
        #pragma unroll
        for (int k = 0; k < 15; ++k) a = fmaf(q[k], S[off::P3 + k * 15 + j], a);
        p[j] = fast_tanhf(a);
    }
    float ph[4];
    #pragma unroll
    for (int j = 0; j < 4; ++j) {
        float a = S[off::PB4 + j];
        #pragma unroll
        for (int k = 0; k < 15; ++k) a = fmaf(p[k], S[off::P4 + k * 4 + j], a);
        ph[j] = a;
    }

    // ---------- vphi at x: r^k sin(k*theta), k = 0.5, 1.0, 1.5 ----------
    const float rr2 = fmaf(x0, x0, x1 * x1);
    const float rr  = sqrtf(rr2);
    const float irr = __fdividef(1.0f, rr);
    const float cc  = x0 * irr, ss = x1 * irr;
    float sh, ch;
    half_angle(cc, ss, sh, ch);
    const float sqr = sqrtf(rr);
    const float vp0 = sqr * sh;                        // r^.5 sin(th/2)
    const float vp1 = rr * ss;                         // r sin(th)
    const float vp2 = (rr * sqr) * fmaf(ss, ch, cc * sh); // r^1.5 sin(1.5 th)

    // ---------- vphi_sig at x_ba (unit vector; |x_ba| == 1 to fp32) ----------
    float shb, chb;
    half_angle(bx, by, shb, chb);
    const float vs0 = shb;
    const float vs1 = by;
    const float vs2 = fmaf(by, chb, bx * shb);

    // ---------- combine ----------
    const float rp = w[0] + yita * w[4]
                   + fmaf(yita, w[5], w[1]) * vp0
                   + fmaf(yita, w[6], w[2]) * vp1
                   + fmaf(yita, w[7], w[3]) * vp2;
    const float sv = ph[0] + ph[1] * vs0 + ph[2] * vs1 + ph[3] * vs2;

    const float lm = S[off::LMB];
    const float rl = (lm == 0.5f) ? sqrtf(r) : __powf(r, lm);

    out[i] = fmaf(sv * yita, rl, rp);
}

extern "C" void kernel_launch(void* const* d_in, const int* in_sizes, int n_in,
                              void* d_out, int out_size) {
    const float* x    = (const float*)d_in[0];
    const float* imv  = (const float*)d_in[1];
    const float* lmbd = (const float*)d_in[2];
    const float* Ww1  = (const float*)d_in[3];
    const float* bw1  = (const float*)d_in[4];
    const float* Ww2  = (const float*)d_in[5];
    const float* bw2  = (const float*)d_in[6];
    const float* Ww3  = (const float*)d_in[7];
    const float* bw3  = (const float*)d_in[8];
    const float* Ww4  = (const float*)d_in[9];
    const float* bw4  = (const float*)d_in[10];
    const float* Wp1  = (const float*)d_in[11];
    const float* bp1  = (const float*)d_in[12];
    const float* Wp2  = (const float*)d_in[13];
    const float* bp2  = (const float*)d_in[14];
    const float* Wp3  = (const float*)d_in[15];
    const float* bp3  = (const float*)d_in[16];
    const float* Wp4  = (const float*)d_in[17];
    const float* bp4  = (const float*)d_in[18];
    float* out = (float*)d_out;

    const int N = out_size;                 // one scalar output per point
    const int blocks = (N + TPB - 1) / TPB;
    mlp_interior_kernel<<<blocks, TPB>>>(
        x, imv, lmbd,
        Ww1, bw1, Ww2, bw2, Ww3, bw3, Ww4, bw4,
        Wp1, bp1, Wp2, bp2, Wp3, bp3, Wp4, bp4,
        out, N);
}

// round 5
// speedup vs baseline: 2.0306x; 2.0306x over previous
#include <cuda_runtime.h>

#define TPB 256

// ---- shared-memory layout (floats), all float4-aligned bases ----
// Hidden weight matrices stored TRANSPOSED [out_j][in_k], rows padded to 32/16.
namespace off {
constexpr int W1  = 0;            // [2][32]   (pad of [2][30])
constexpr int B1  = 64;           // [32]
constexpr int W2T = 96;           // [30][32]
constexpr int B2  = 1056;         // [32]
constexpr int W3T = 1088;         // [30][32]
constexpr int B3  = 2048;         // [32]
constexpr int W4T = 2080;         // [8][32]
constexpr int B4  = 2336;         // [8]
constexpr int P1  = 2344;         // [2][32]   (pad of [2][15])
constexpr int PB1 = 2408;         // [16]
constexpr int P2T = 2424;         // [15][16]
constexpr int PB2 = 2664;         // [16]
constexpr int P3T = 2680;         // [15][16]
constexpr int PB3 = 2920;         // [16]
constexpr int P4T = 2936;         // [4][16]
constexpr int PB4 = 3000;         // [4]
constexpr int IMV = 3004;         // [2]
constexpr int LMB = 3006;         // [1]
constexpr int TOTAL = 3008;
}

// tanh via EX2 + fast divide (~1e-7 abs err)
__device__ __forceinline__ float fast_tanhf(float v) {
    float a = fabsf(v);
    float e = __expf(-2.0f * a);
    float r = __fdividef(1.0f - e, 1.0f + e);
    return copysignf(r, v);
}

// Branchless half-angle: (c,s) on unit circle -> sin(th/2), cos(th/2).
__device__ __forceinline__ void half_angle(float c, float s, float& sh, float& ch) {
    float root = sqrtf(0.5f * (1.0f + fabsf(c)));   // |ch| if c>=0, |sh| if c<0
    float q    = __fdividef(s, 2.0f * root);
    bool pos   = (c >= 0.0f);
    sh = pos ? q    : copysignf(root, s);
    ch = pos ? root : fabsf(q);
}

__global__ void __launch_bounds__(TPB)
mlp_interior_kernel(
    const float* __restrict__ x,
    const float* __restrict__ imv,
    const float* __restrict__ lmbd,
    const float* __restrict__ Ww1, const float* __restrict__ bw1,
    const float* __restrict__ Ww2, const float* __restrict__ bw2,
    const float* __restrict__ Ww3, const float* __restrict__ bw3,
    const float* __restrict__ Ww4, const float* __restrict__ bw4,
    const float* __restrict__ Wp1, const float* __restrict__ bp1,
    const float* __restrict__ Wp2, const float* __restrict__ bp2,
    const float* __restrict__ Wp3, const float* __restrict__ bp3,
    const float* __restrict__ Wp4, const float* __restrict__ bp4,
    float* __restrict__ out, int N)
{
    __shared__ float S[off::TOTAL];
    const int tid = threadIdx.x;

    // zero everything (covers the pad lanes), then fill with transposes
    for (int k = tid; k < off::TOTAL; k += TPB) S[k] = 0.0f;
    __syncthreads();

    for (int t = tid; t < 60; t += TPB)  S[off::W1  + (t / 30) * 32 + (t % 30)] = Ww1[t];
    for (int t = tid; t < 30; t += TPB)  S[off::B1  + t] = bw1[t];
    for (int t = tid; t < 900; t += TPB) S[off::W2T + (t % 30) * 32 + (t / 30)] = Ww2[t];
    for (int t = tid; t < 30; t += TPB)  S[off::B2  + t] = bw2[t];
    for (int t = tid; t < 900; t += TPB) S[off::W3T + (t % 30) * 32 + (t / 30)] = Ww3[t];
    for (int t = tid; t < 30; t += TPB)  S[off::B3  + t] = bw3[t];
    for (int t = tid; t < 240; t += TPB) S[off::W4T + (t % 8) * 32 + (t / 8)]   = Ww4[t];
    for (int t = tid; t < 8;  t += TPB)  S[off::B4  + t] = bw4[t];
    for (int t = tid; t < 30; t += TPB)  S[off::P1  + (t / 15) * 32 + (t % 15)] = Wp1[t];
    for (int t = tid; t < 15; t += TPB)  S[off::PB1 + t] = bp1[t];
    for (int t = tid; t < 225; t += TPB) S[off::P2T + (t % 15) * 16 + (t / 15)] = Wp2[t];
    for (int t = tid; t < 15; t += TPB)  S[off::PB2 + t] = bp2[t];
    for (int t = tid; t < 225; t += TPB) S[off::P3T + (t % 15) * 16 + (t / 15)] = Wp3[t];
    for (int t = tid; t < 15; t += TPB)  S[off::PB3 + t] = bp3[t];
    for (int t = tid; t < 60; t += TPB)  S[off::P4T + (t % 4) * 16 + (t / 4)]   = Wp4[t];
    for (int t = tid; t < 4;  t += TPB)  S[off::PB4 + t] = bp4[t];
    if (tid == 0) {
        S[off::IMV]     = imv[0];
        S[off::IMV + 1] = imv[1];
        S[off::LMB]     = lmbd[0];
    }
    __syncthreads();

    const int i = blockIdx.x * TPB + tid;
    if (i >= N) return;

    const float2 xv = reinterpret_cast<const float2*>(x)[i];
    const float x0 = xv.x, x1 = xv.y;

    // ---------- w MLP: 2 -> 30 -> 30 -> 30 -> 8 ----------
    float h[32], g[32];
    #pragma unroll
    for (int c = 0; c < 8; ++c) {
        float4 w0 = *reinterpret_cast<const float4*>(&S[off::W1 + 4 * c]);
        float4 w1 = *reinterpret_cast<const float4*>(&S[off::W1 + 32 + 4 * c]);
        float4 bb = *reinterpret_cast<const float4*>(&S[off::B1 + 4 * c]);
        h[4 * c + 0] = fast_tanhf(fmaf(x0, w0.x, fmaf(x1, w1.x, bb.x)));
        h[4 * c + 1] = fast_tanhf(fmaf(x0, w0.y, fmaf(x1, w1.y, bb.y)));
        h[4 * c + 2] = fast_tanhf(fmaf(x0, w0.z, fmaf(x1, w1.z, bb.z)));
        h[4 * c + 3] = fast_tanhf(fmaf(x0, w0.w, fmaf(x1, w1.w, bb.w)));
    }
    #pragma unroll
    for (int j = 0; j < 30; ++j) {
        const float4* row = reinterpret_cast<const float4*>(&S[off::W2T + j * 32]);
        float a0 = 0.f, a1 = 0.f, a2 = 0.f, a3 = 0.f;
        #pragma unroll
        for (int c = 0; c < 8; ++c) {
            float4 wv = row[c];
            a0 = fmaf(h[4 * c + 0], wv.x, a0);
            a1 = fmaf(h[4 * c + 1], wv.y, a1);
            a2 = fmaf(h[4 * c + 2], wv.z, a2);
            a3 = fmaf(h[4 * c + 3], wv.w, a3);
        }
        g[j] = fast_tanhf(((a0 + a1) + (a2 + a3)) + S[off::B2 + j]);
    }
    g[30] = 0.0f; g[31] = 0.0f;          // pad lanes read by next layer
    #pragma unroll
    for (int j = 0; j < 30; ++j) {
        const float4* row = reinterpret_cast<const float4*>(&S[off::W3T + j * 32]);
        float a0 = 0.f, a1 = 0.f, a2 = 0.f, a3 = 0.f;
        #pragma unroll
        for (int c = 0; c < 8; ++c) {
            float4 wv = row[c];
            a0 = fmaf(g[4 * c + 0], wv.x, a0);
            a1 = fmaf(g[4 * c + 1], wv.y, a1);
            a2 = fmaf(g[4 * c + 2], wv.z, a2);
            a3 = fmaf(g[4 * c + 3], wv.w, a3);
        }
        h[j] = fast_tanhf(((a0 + a1) + (a2 + a3)) + S[off::B3 + j]);
    }
    h[30] = 0.0f; h[31] = 0.0f;          // pad lanes read by layer 4
    float w[8];
    #pragma unroll
    for (int j = 0; j < 8; ++j) {
        const float4* row = reinterpret_cast<const float4*>(&S[off::W4T + j * 32]);
        float a0 = 0.f, a1 = 0.f, a2 = 0.f, a3 = 0.f;
        #pragma unroll
        for (int c = 0; c < 8; ++c) {
            float4 wv = row[c];
            a0 = fmaf(h[4 * c + 0], wv.x, a0);
            a1 = fmaf(h[4 * c + 1], wv.y, a1);
            a2 = fmaf(h[4 * c + 2], wv.z, a2);
            a3 = fmaf(h[4 * c + 3], wv.w, a3);
        }
        w[j] = ((a0 + a1) + (a2 + a3)) + S[off::B4 + j];
    }

    // ---------- geometry ----------
    const float d0 = x0 - S[off::IMV], d1 = x1 - S[off::IMV + 1];
    const float r2 = fmaf(d0, d0, d1 * d1);
    const float r  = sqrtf(r2);
    const float ir = __fdividef(1.0f, r);
    const float bx = d0 * ir, by = d1 * ir;

    const float t  = fminf(fmaxf(fmaf(2.5f, r, -1.25f), 0.0f), 1.0f);
    const float t3 = t * t * t;
    const float yita = fmaf(fmaf(fmaf(-6.0f, t, 15.0f), t, -10.0f), t3, 1.0f);

    // ---------- phi MLP on unit vector: 2 -> 15 -> 15 -> 15 -> 4 ----------
    float p[16], q[16];
    #pragma unroll
    for (int c = 0; c < 4; ++c) {
        float4 w0 = *reinterpret_cast<const float4*>(&S[off::P1 + 4 * c]);
        float4 w1 = *reinterpret_cast<const float4*>(&S[off::P1 + 32 + 4 * c]);
        float4 bb = *reinterpret_cast<const float4*>(&S[off::PB1 + 4 * c]);
        p[4 * c + 0] = fast_tanhf(fmaf(bx, w0.x, fmaf(by, w1.x, bb.x)));
        p[4 * c + 1] = fast_tanhf(fmaf(bx, w0.y, fmaf(by, w1.y, bb.y)));
        p[4 * c + 2] = fast_tanhf(fmaf(bx, w0.z, fmaf(by, w1.z, bb.z)));
        p[4 * c + 3] = fast_tanhf(fmaf(bx, w0.w, fmaf(by, w1.w, bb.w)));
    }
    #pragma unroll
    for (int j = 0; j < 15; ++j) {
        const float4* row = reinterpret_cast<const float4*>(&S[off::P2T + j * 16]);
        float a0 = 0.f, a1 = 0.f, a2 = 0.f, a3 = 0.f;
        #pragma unroll
        for (int c = 0; c < 4; ++c) {
            float4 wv = row[c];
            a0 = fmaf(p[4 * c + 0], wv.x, a0);
            a1 = fmaf(p[4 * c + 1], wv.y, a1);
            a2 = fmaf(p[4 * c + 2], wv.z, a2);
            a3 = fmaf(p[4 * c + 3], wv.w, a3);
        }
        q[j] = fast_tanhf(((a0 + a1) + (a2 + a3)) + S[off::PB2 + j]);
    }
    q[15] = 0.0f;                        // pad lane read by next layer
    #pragma unroll
    for (int j = 0; j < 15; ++j) {
        const float4* row = reinterpret_cast<const float4*>(&S[off::P3T + j * 16]);
        float a0 = 0.f, a1 = 0.f, a2 = 0.f, a3 = 0.f;
        #pragma unroll
        for (int c = 0; c < 4; ++c) {
            float4 wv = row[c];
            a0 = fmaf(q[4 * c + 0], wv.x, a0);
            a1 = fmaf(q[4 * c + 1], wv.y, a1);
            a2 = fmaf(q[4 * c + 2], wv.z, a2);
            a3 = fmaf(q[4 * c + 3], wv.w, a3);
        }
        p[j] = fast_tanhf(((a0 + a1) + (a2 + a3)) + S[off::PB3 + j]);
    }
    p[15] = 0.0f;                        // pad lane read by layer 4
    float ph[4];
    #pragma unroll
    for (int j = 0; j < 4; ++j) {
        const float4* row = reinterpret_cast<const float4*>(&S[off::P4T + j * 16]);
        float a0 = 0.f, a1 = 0.f, a2 = 0.f, a3 = 0.f;
        #pragma unroll
        for (int c = 0; c < 4; ++c) {
            float4 wv = row[c];
            a0 = fmaf(p[4 * c + 0], wv.x, a0);
            a1 = fmaf(p[4 * c + 1], wv.y, a1);
            a2 = fmaf(p[4 * c + 2], wv.z, a2);
            a3 = fmaf(p[4 * c + 3], wv.w, a3);
        }
        ph[j] = ((a0 + a1) + (a2 + a3)) + S[off::PB4 + j];
    }

    // ---------- vphi at x: r^k sin(k*theta), k = 0.5, 1.0, 1.5 ----------
    const float rr2 = fmaf(x0, x0, x1 * x1);
    const float rr  = sqrtf(rr2);
    const float irr = __fdividef(1.0f, rr);
    const float cc  = x0 * irr, ss = x1 * irr;
    float sh, ch;
    half_angle(cc, ss, sh, ch);
    const float sqr = sqrtf(rr);
    const float vp0 = sqr * sh;
    const float vp1 = rr * ss;
    const float vp2 = (rr * sqr) * fmaf(ss, ch, cc * sh);

    // ---------- vphi_sig at x_ba ----------
    float shb, chb;
    half_angle(bx, by, shb, chb);
    const float vs2 = fmaf(by, chb, bx * shb);

    // ---------- combine ----------
    const float rp = w[0] + yita * w[4]
                   + fmaf(yita, w[5], w[1]) * vp0
                   + fmaf(yita, w[6], w[2]) * vp1
                   + fmaf(yita, w[7], w[3]) * vp2;
    const float sv = ph[0] + ph[1] * shb + ph[2] * by + ph[3] * vs2;

    const float lm = S[off::LMB];
    const float rl = (lm == 0.5f) ? sqrtf(r) : __powf(r, lm);

    out[i] = fmaf(sv * yita, rl, rp);
}

extern "C" void kernel_launch(void* const* d_in, const int* in_sizes, int n_in,
                              void* d_out, int out_size) {
    const float* x    = (const float*)d_in[0];
    const float* imv  = (const float*)d_in[1];
    const float* lmbd = (const float*)d_in[2];
    const float* Ww1  = (const float*)d_in[3];
    const float* bw1  = (const float*)d_in[4];
    const float* Ww2  = (const float*)d_in[5];
    const float* bw2  = (const float*)d_in[6];
    const float* Ww3  = (const float*)d_in[7];
    const float* bw3  = (const float*)d_in[8];
    const float* Ww4  = (const float*)d_in[9];
    const float* bw4  = (const float*)d_in[10];
    const float* Wp1  = (const float*)d_in[11];
    const float* bp1  = (const float*)d_in[12];
    const float* Wp2  = (const float*)d_in[13];
    const float* bp2  = (const float*)d_in[14];
    const float* Wp3  = (const float*)d_in[15];
    const float* bp3  = (const float*)d_in[16];
    const float* Wp4  = (const float*)d_in[17];
    const float* bp4  = (const float*)d_in[18];
    float* out = (float*)d_out;

    const int N = out_size;
    const int blocks = (N + TPB - 1) / TPB;
    mlp_interior_kernel<<<blocks, TPB>>>(
        x, imv, lmbd,
        Ww1, bw1, Ww2, bw2, Ww3, bw3, Ww4, bw4,
        Wp1, bp1, Wp2, bp2, Wp3, bp3, Wp4, bp4,
        out, N);
}